// round 13
// baseline (speedup 1.0000x reference)
#include <cuda_runtime.h>
#include <cuda_fp16.h>

// ---------------- problem-size capacities (fixed by the dataset) -------------
#define MAXN 50000
#define MAXE 800000
#define MAXET (MAXN + MAXE)
#define SCAN_CHUNK 4096

// ---------------- f32x2 packed-FMA helpers (sm_103a FFMA2) -------------------
#define PACK_DUP(d, x)   asm("mov.b64 %0, {%1, %1};" : "=l"(d) : "f"(x))
#define FMA2(acc, a, b)  asm("fma.rn.f32x2 %0, %1, %2, %0;" : "+l"(acc) : "l"(a), "l"(b))
#define UNPACK2(lo, hi, d) asm("mov.b64 {%0, %1}, %2;" : "=f"(lo), "=f"(hi) : "l"(d))

// ---------------- device scratch (no allocation allowed) ---------------------
__device__ __half g_h1h[MAXN * 128];   // x @ W1   (fp16, gather-only)
__device__ float  g_h2[MAXN * 128];    // elu(layer1 out)  (fp32, GEMM input)
__device__ __half g_hmlh[MAXN * 64];   // interleaved [mu_c, lv_c], fp16, gather-only
__device__ float  g_asrc1[MAXN * 2];   // layer1 per-node att dots (2 heads)
__device__ float  g_adst1[MAXN * 2];
__device__ float2 g_a2s[MAXN];         // {a_src_mu, a_src_lv}
__device__ float2 g_a2d[MAXN];         // {a_dst_mu, a_dst_lv}
__device__ int    g_counts[MAXN];      // STAYS ZERO between calls (self-cleaning scan)
__device__ int    g_row[MAXN + 1];
__device__ int    g_cursor[MAXN];
__device__ int    g_srcs[MAXET];       // CSR (by dst) of source node ids
__device__ int    g_dsts[MAXET];       // CSR slot -> dst node id
__device__ float4 g_e1[MAXET];         // per-edge {w0, w1, src_bits, -} layer 1
__device__ float4 g_e2[MAXET];         // per-edge {wmu, wlv, src_bits, -} layer 2

// ---------------- CSR build --------------------------------------------------
__global__ void hist_kernel(const int* __restrict__ ei, int E, int N) {
    int e = blockIdx.x * blockDim.x + threadIdx.x;
    int ET = E + N;
    if (e >= ET) return;
    int dst = (e < E) ? ei[E + e] : (e - E);   // self-loop tail
    atomicAdd(&g_counts[dst], 1);
}

// single-block scan over g_counts; also zeroes g_counts for the next call
__global__ void scan_kernel(int n, int total) {
    int t = threadIdx.x, lane = t & 31, warp = t >> 5;
    __shared__ int ws[32];
    __shared__ int s_carry, s_total;
    if (t == 0) s_carry = 0;
    __syncthreads();
    for (int base = 0; base < n; base += SCAN_CHUNK) {
        int idx = base + t * 4;
        int v[4]; int s = 0;
#pragma unroll
        for (int j = 0; j < 4; j++) { v[j] = (idx + j < n) ? g_counts[idx + j] : 0; s += v[j]; }
        int incl = s;
#pragma unroll
        for (int off = 1; off < 32; off <<= 1) {
            int y = __shfl_up_sync(0xffffffffu, incl, off);
            if (lane >= off) incl += y;
        }
        if (lane == 31) ws[warp] = incl;
        __syncthreads();
        if (warp == 0) {
            int wv = ws[lane];
            int winc = wv;
#pragma unroll
            for (int off = 1; off < 32; off <<= 1) {
                int y = __shfl_up_sync(0xffffffffu, winc, off);
                if (lane >= off) winc += y;
            }
            ws[lane] = winc - wv;
            if (lane == 31) s_total = winc;
        }
        __syncthreads();
        int running = s_carry + ws[warp] + (incl - s);
#pragma unroll
        for (int j = 0; j < 4; j++) {
            int i = idx + j;
            if (i < n) { g_row[i] = running; g_cursor[i] = running; g_counts[i] = 0; }
            running += v[j];
        }
        __syncthreads();
        if (t == 0) s_carry += s_total;
    }
    if (t == 0) g_row[n] = total;
}

__global__ void scatter_kernel(const int* __restrict__ ei, int E, int N) {
    int e = blockIdx.x * blockDim.x + threadIdx.x;
    int ET = E + N;
    if (e >= ET) return;
    int src, dst;
    if (e < E) { src = ei[e]; dst = ei[E + e]; }
    else       { src = e - E; dst = e - E; }
    int pos = atomicAdd(&g_cursor[dst], 1);
    g_srcs[pos] = src;
    g_dsts[pos] = dst;
}

// ------- per-edge weight precompute (device-global tables, coalesced I/O) ----
__global__ void weight1_kernel(int ET) {
    int e = blockIdx.x * blockDim.x + threadIdx.x;
    if (e >= ET) return;
    int s = g_srcs[e], d = g_dsts[e];
    float2 a = ((const float2*)g_asrc1)[s];
    float2 b = ((const float2*)g_adst1)[d];
    float l0 = a.x + b.x; l0 = l0 > 0.f ? l0 : 0.2f * l0;
    float l1 = a.y + b.y; l1 = l1 > 0.f ? l1 : 0.2f * l1;
    g_e1[e] = make_float4(__expf(l0), __expf(l1), __int_as_float(s), 0.f);
}

__global__ void weight2_kernel(int ET) {
    int e = blockIdx.x * blockDim.x + threadIdx.x;
    if (e >= ET) return;
    int s = g_srcs[e], d = g_dsts[e];
    float2 a = g_a2s[s];
    float2 b = g_a2d[d];
    float l0 = a.x + b.x; l0 = l0 > 0.f ? l0 : 0.2f * l0;
    float l1 = a.y + b.y; l1 = l1 > 0.f ? l1 : 0.2f * l1;
    g_e2[e] = make_float4(__expf(l0), __expf(l1), __int_as_float(s), 0.f);
}

// ------- GEMM1: g_h1h = half(x @ W1), FFMA2 inner loop, fused att dots -------
__global__ void gemm1_kernel(const float* __restrict__ A, const float* __restrict__ B,
                             const float* __restrict__ att_src, const float* __restrict__ att_dst,
                             int M) {
    constexpr int BM = 64, BK = 32, BN = 128;
    constexpr int TX = 32, TY = 8, RPT = 8, NP = RPT / 2;
    __shared__ __align__(16) float As[BK][BM + 2];   // row = 264B (8B-aligned)
    __shared__ __align__(16) float Bs[BK][BN];
    int t = threadIdx.x;
    int tx = t % TX, ty = t / TX;
    int row0 = blockIdx.x * BM;
    unsigned long long acc[NP][4];
#pragma unroll
    for (int p = 0; p < NP; p++)
#pragma unroll
        for (int c = 0; c < 4; c++) acc[p][c] = 0ull;

    for (int k0 = 0; k0 < 128; k0 += BK) {
        for (int i = t; i < BM * BK; i += 256) {
            int r = i / BK, kk = i % BK;
            int gr = row0 + r;
            As[kk][r] = (gr < M) ? A[gr * 128 + k0 + kk] : 0.f;
        }
        for (int i = t; i < BK * BN; i += 256) {
            int kk = i / BN, c = i % BN;
            Bs[kk][c] = B[(k0 + kk) * BN + c];
        }
        __syncthreads();
#pragma unroll
        for (int kk = 0; kk < BK; kk++) {
            float4 bv = *(const float4*)&Bs[kk][tx * 4];
            unsigned long long bxx, byy, bzz, bww;
            PACK_DUP(bxx, bv.x); PACK_DUP(byy, bv.y);
            PACK_DUP(bzz, bv.z); PACK_DUP(bww, bv.w);
#pragma unroll
            for (int p = 0; p < NP; p++) {
                unsigned long long av = *(const unsigned long long*)&As[kk][ty * RPT + 2 * p];
                FMA2(acc[p][0], av, bxx);
                FMA2(acc[p][1], av, byy);
                FMA2(acc[p][2], av, bzz);
                FMA2(acc[p][3], av, bww);
            }
        }
        __syncthreads();
    }
    float4 asv = *(const float4*)&att_src[tx * 4];
    float4 adv = *(const float4*)&att_dst[tx * 4];
#pragma unroll
    for (int p = 0; p < NP; p++) {
        float v0[4], v1[4];
#pragma unroll
        for (int c = 0; c < 4; c++) UNPACK2(v0[c], v1[c], acc[p][c]);
#pragma unroll
        for (int h = 0; h < 2; h++) {
            float* v = h ? v1 : v0;
            int gr = row0 + ty * RPT + 2 * p + h;
            bool ok = gr < M;
            if (ok) {
                __half2 p0 = __floats2half2_rn(v[0], v[1]);
                __half2 p1 = __floats2half2_rn(v[2], v[3]);
                uint2 pk;
                pk.x = *(unsigned int*)&p0;
                pk.y = *(unsigned int*)&p1;
                *(uint2*)&g_h1h[gr * 128 + tx * 4] = pk;
            }
            float ps = v[0] * asv.x + v[1] * asv.y + v[2] * asv.z + v[3] * asv.w;
            float pd = v[0] * adv.x + v[1] * adv.y + v[2] * adv.z + v[3] * adv.w;
#pragma unroll
            for (int off = 1; off < 16; off <<= 1) {   // reduce within 16-lane halves
                ps += __shfl_xor_sync(0xffffffffu, ps, off);
                pd += __shfl_xor_sync(0xffffffffu, pd, off);
            }
            if ((tx & 15) == 0 && ok) {
                g_asrc1[gr * 2 + (tx >> 4)] = ps;
                g_adst1[gr * 2 + (tx >> 4)] = pd;
            }
        }
    }
}

// ---------------- layer-1 softmax + aggregation + bias + ELU -----------------
__global__ void agg1_kernel(const float* __restrict__ b1, int N) {
    int gid = blockIdx.x * blockDim.x + threadIdx.x;
    int n = gid >> 5, lane = gid & 31;
    if (n >= N) return;
    int start = g_row[n], end = g_row[n + 1];
    int cb = lane * 4;
    bool head1 = lane >= 16;

    // single pass: uniform edge-record loads; every lane sums the denominators
    float a0 = 0.f, a1 = 0.f, a2 = 0.f, a3 = 0.f, s0 = 0.f, s1 = 0.f;
    int i = start;
    for (; i + 3 < end; i += 4) {
#pragma unroll
        for (int j = 0; j < 4; j++) {
            float4 e = g_e1[i + j];
            int s = __float_as_int(e.z);
            s0 += e.x; s1 += e.y;
            float w = head1 ? e.y : e.x;
            uint2 raw = *(const uint2*)&g_h1h[s * 128 + cb];
            float2 f0 = __half22float2(*(__half2*)&raw.x);
            float2 f1 = __half22float2(*(__half2*)&raw.y);
            a0 = fmaf(w, f0.x, a0);
            a1 = fmaf(w, f0.y, a1);
            a2 = fmaf(w, f1.x, a2);
            a3 = fmaf(w, f1.y, a3);
        }
    }
    for (; i < end; i++) {
        float4 e = g_e1[i];
        int s = __float_as_int(e.z);
        s0 += e.x; s1 += e.y;
        float w = head1 ? e.y : e.x;
        uint2 raw = *(const uint2*)&g_h1h[s * 128 + cb];
        float2 f0 = __half22float2(*(__half2*)&raw.x);
        float2 f1 = __half22float2(*(__half2*)&raw.y);
        a0 = fmaf(w, f0.x, a0);
        a1 = fmaf(w, f0.y, a1);
        a2 = fmaf(w, f1.x, a2);
        a3 = fmaf(w, f1.y, a3);
    }
    float inv = 1.f / ((head1 ? s1 : s0) + 1e-16f);
    float4 bb = *(const float4*)&b1[cb];
    float o0 = a0 * inv + bb.x; o0 = o0 > 0.f ? o0 : __expf(o0) - 1.f;
    float o1 = a1 * inv + bb.y; o1 = o1 > 0.f ? o1 : __expf(o1) - 1.f;
    float o2 = a2 * inv + bb.z; o2 = o2 > 0.f ? o2 : __expf(o2) - 1.f;
    float o3 = a3 * inv + bb.w; o3 = o3 > 0.f ? o3 : __expf(o3) - 1.f;
    *(float4*)&g_h2[n * 128 + cb] = make_float4(o0, o1, o2, o3);
}

// ------- fused mu+lv GEMM (FFMA2): g_hmlh = half(h2 @ [Wmu|Wlv]) + dots ------
__global__ void gemm_mulv_kernel(const float* __restrict__ Bmu, const float* __restrict__ Blv,
                                 const float* __restrict__ asmu, const float* __restrict__ admu,
                                 const float* __restrict__ aslv, const float* __restrict__ adlv,
                                 int M) {
    constexpr int BM = 64, BK = 32, BN = 64;
    constexpr int TX = 16, TY = 16, RPT = 4, NP = RPT / 2;
    __shared__ __align__(16) float As[BK][BM + 2];
    __shared__ __align__(16) float Bs[BK][BN];
    int t = threadIdx.x;
    int tx = t % TX, ty = t / TX;
    int row0 = blockIdx.x * BM;
    unsigned long long acc[NP][4];
#pragma unroll
    for (int p = 0; p < NP; p++)
#pragma unroll
        for (int c = 0; c < 4; c++) acc[p][c] = 0ull;

    for (int k0 = 0; k0 < 128; k0 += BK) {
        for (int i = t; i < BM * BK; i += 256) {
            int r = i / BK, kk = i % BK;
            int gr = row0 + r;
            As[kk][r] = (gr < M) ? g_h2[gr * 128 + k0 + kk] : 0.f;
        }
        for (int i = t; i < BK * BN; i += 256) {
            int kk = i / BN, c = i % BN;
            Bs[kk][c] = (c < 32) ? Bmu[(k0 + kk) * 32 + c] : Blv[(k0 + kk) * 32 + (c - 32)];
        }
        __syncthreads();
#pragma unroll
        for (int kk = 0; kk < BK; kk++) {
            float4 bv = *(const float4*)&Bs[kk][tx * 4];
            unsigned long long bxx, byy, bzz, bww;
            PACK_DUP(bxx, bv.x); PACK_DUP(byy, bv.y);
            PACK_DUP(bzz, bv.z); PACK_DUP(bww, bv.w);
#pragma unroll
            for (int p = 0; p < NP; p++) {
                unsigned long long av = *(const unsigned long long*)&As[kk][ty * RPT + 2 * p];
                FMA2(acc[p][0], av, bxx);
                FMA2(acc[p][1], av, byy);
                FMA2(acc[p][2], av, bzz);
                FMA2(acc[p][3], av, bww);
            }
        }
        __syncthreads();
    }
    bool islv = tx >= 8;
    int c0 = (tx * 4) & 31;   // channel base within the 32-dim latent
    float4 asv = islv ? *(const float4*)&aslv[c0] : *(const float4*)&asmu[c0];
    float4 adv = islv ? *(const float4*)&adlv[c0] : *(const float4*)&admu[c0];
#pragma unroll
    for (int p = 0; p < NP; p++) {
        float v0[4], v1[4];
#pragma unroll
        for (int c = 0; c < 4; c++) UNPACK2(v0[c], v1[c], acc[p][c]);
#pragma unroll
        for (int h = 0; h < 2; h++) {
            float* v = h ? v1 : v0;
            int gr = row0 + ty * RPT + 2 * p + h;
            bool ok = gr < M;
            if (ok) {
                g_hmlh[gr * 64 + 2 * (c0 + 0) + islv] = __float2half_rn(v[0]);
                g_hmlh[gr * 64 + 2 * (c0 + 1) + islv] = __float2half_rn(v[1]);
                g_hmlh[gr * 64 + 2 * (c0 + 2) + islv] = __float2half_rn(v[2]);
                g_hmlh[gr * 64 + 2 * (c0 + 3) + islv] = __float2half_rn(v[3]);
            }
            float ps = v[0] * asv.x + v[1] * asv.y + v[2] * asv.z + v[3] * asv.w;
            float pd = v[0] * adv.x + v[1] * adv.y + v[2] * adv.z + v[3] * adv.w;
#pragma unroll
            for (int off = 1; off < 8; off <<= 1) {    // reduce within 8-lane subgroup
                ps += __shfl_xor_sync(0xffffffffu, ps, off);
                pd += __shfl_xor_sync(0xffffffffu, pd, off);
            }
            float os = __shfl_xor_sync(0xffffffffu, ps, 8);  // other net's sum
            float od = __shfl_xor_sync(0xffffffffu, pd, 8);
            if ((t & 15) == 0 && ok) {
                g_a2s[gr] = make_float2(ps, os);   // {mu, lv}
                g_a2d[gr] = make_float2(pd, od);
            }
        }
    }
}

// ---------------- mu + lv softmax + aggregation (fused), writes output -------
__global__ void agg2_kernel(const float* __restrict__ bmu, const float* __restrict__ blv,
                            float* __restrict__ out, int N) {
    int gid = blockIdx.x * blockDim.x + threadIdx.x;
    int n = gid >> 5, lane = gid & 31;
    if (n >= N) return;
    int start = g_row[n], end = g_row[n + 1];

    float accm = 0.f, accl = 0.f, sm = 0.f, sl = 0.f;
    int i = start;
    for (; i + 3 < end; i += 4) {
#pragma unroll
        for (int j = 0; j < 4; j++) {
            float4 e = g_e2[i + j];
            int s = __float_as_int(e.z);
            sm += e.x; sl += e.y;
            __half2 hv = *(const __half2*)&g_hmlh[s * 64 + lane * 2];  // {mu_c, lv_c}
            float2 f = __half22float2(hv);
            accm = fmaf(e.x, f.x, accm);
            accl = fmaf(e.y, f.y, accl);
        }
    }
    for (; i < end; i++) {
        float4 e = g_e2[i];
        int s = __float_as_int(e.z);
        sm += e.x; sl += e.y;
        __half2 hv = *(const __half2*)&g_hmlh[s * 64 + lane * 2];
        float2 f = __half22float2(hv);
        accm = fmaf(e.x, f.x, accm);
        accl = fmaf(e.y, f.y, accl);
    }
    out[n * 32 + lane]          = accm / (sm + 1e-16f) + bmu[lane];
    out[N * 32 + n * 32 + lane] = accl / (sl + 1e-16f) + blv[lane];
}

// ---------------- launch -----------------------------------------------------
extern "C" void kernel_launch(void* const* d_in, const int* in_sizes, int n_in,
                              void* d_out, int out_size) {
    const float* x          = (const float*)d_in[0];
    const int*   ei         = (const int*)d_in[1];
    const float* W1         = (const float*)d_in[2];
    const float* att_src1   = (const float*)d_in[3];
    const float* att_dst1   = (const float*)d_in[4];
    const float* b1         = (const float*)d_in[5];
    const float* Wmu        = (const float*)d_in[6];
    const float* att_src_mu = (const float*)d_in[7];
    const float* att_dst_mu = (const float*)d_in[8];
    const float* bmu        = (const float*)d_in[9];
    const float* Wlv        = (const float*)d_in[10];
    const float* att_src_lv = (const float*)d_in[11];
    const float* att_dst_lv = (const float*)d_in[12];
    const float* blv        = (const float*)d_in[13];
    float* out = (float*)d_out;

    int N = in_sizes[0] / 128;
    int E = in_sizes[1] / 2;
    int ET = E + N;

    const int TB = 256;
    int warpBlocks = (N * 32 + TB - 1) / TB;
    int edgeBlocks = (ET + TB - 1) / TB;

    // lazily created once (on the uncaptured correctness call); reused in capture
    static cudaStream_t s1 = nullptr;
    static cudaEvent_t evFork = nullptr, evJoin = nullptr;
    if (s1 == nullptr) {
        cudaStreamCreateWithFlags(&s1, cudaStreamNonBlocking);
        cudaEventCreateWithFlags(&evFork, cudaEventDisableTiming);
        cudaEventCreateWithFlags(&evJoin, cudaEventDisableTiming);
    }

    // fork: CSR build on s1, gemm1 on the main stream, join before weight1
    cudaEventRecord(evFork, 0);
    cudaStreamWaitEvent(s1, evFork, 0);

    hist_kernel<<<edgeBlocks, TB, 0, s1>>>(ei, E, N);
    scan_kernel<<<1, 1024, 0, s1>>>(N, ET);
    scatter_kernel<<<edgeBlocks, TB, 0, s1>>>(ei, E, N);

    gemm1_kernel<<<(N + 63) / 64, TB>>>(x, W1, att_src1, att_dst1, N);

    cudaEventRecord(evJoin, s1);
    cudaStreamWaitEvent(0, evJoin, 0);

    // layer 1: per-edge weights, then lean aggregation
    weight1_kernel<<<edgeBlocks, TB>>>(ET);
    agg1_kernel<<<warpBlocks, TB>>>(b1, N);

    // mu + logvar: fused projection GEMM (+dots), weights, fused aggregation
    gemm_mulv_kernel<<<(N + 63) / 64, TB>>>(Wmu, Wlv, att_src_mu, att_dst_mu,
                                            att_src_lv, att_dst_lv, N);
    weight2_kernel<<<edgeBlocks, TB>>>(ET);
    agg2_kernel<<<warpBlocks, TB>>>(bmu, blv, out, N);
}

// round 14
// speedup vs baseline: 1.4194x; 1.4194x over previous
#include <cuda_runtime.h>
#include <cuda_fp16.h>

// ---------------- problem-size capacities (fixed by the dataset) -------------
#define MAXN 50000
#define MAXE 800000
#define MAXET (MAXN + MAXE)
#define SCAN_CHUNK 4096

// ---------------- device scratch (no allocation allowed) ---------------------
__device__ __half g_h1h[MAXN * 128];   // x @ W1   (fp16, gather-only)
__device__ float  g_h2[MAXN * 128];    // elu(layer1 out)  (fp32, GEMM input)
__device__ __half g_hmlh[MAXN * 64];   // interleaved [mu_c, lv_c], fp16, gather-only
__device__ float  g_asrc1[MAXN * 2];   // layer1 per-node att dots (2 heads)
__device__ float  g_adst1[MAXN * 2];
__device__ float2 g_a2s[MAXN];         // {a_src_mu, a_src_lv}
__device__ float2 g_a2d[MAXN];         // {a_dst_mu, a_dst_lv}
__device__ int    g_counts[MAXN];      // STAYS ZERO between calls (self-cleaning scan)
__device__ int    g_row[MAXN + 1];
__device__ int    g_cursor[MAXN];
__device__ int    g_srcs[MAXET];       // CSR (by dst) of source node ids
__device__ int    g_dsts[MAXET];       // CSR slot -> dst node id
__device__ float4 g_e1[MAXET];         // per-edge {w0, w1, src_bits, -} layer 1
__device__ float4 g_e2[MAXET];         // per-edge {wmu, wlv, src_bits, -} layer 2

// ---------------- CSR build --------------------------------------------------
__global__ void hist_kernel(const int* __restrict__ ei, int E, int N) {
    int e = blockIdx.x * blockDim.x + threadIdx.x;
    int ET = E + N;
    if (e >= ET) return;
    int dst = (e < E) ? ei[E + e] : (e - E);   // self-loop tail
    atomicAdd(&g_counts[dst], 1);
}

// single-block scan over g_counts; also zeroes g_counts for the next call
__global__ void scan_kernel(int n, int total) {
    int t = threadIdx.x, lane = t & 31, warp = t >> 5;
    __shared__ int ws[32];
    __shared__ int s_carry, s_total;
    if (t == 0) s_carry = 0;
    __syncthreads();
    for (int base = 0; base < n; base += SCAN_CHUNK) {
        int idx = base + t * 4;
        int v[4]; int s = 0;
#pragma unroll
        for (int j = 0; j < 4; j++) { v[j] = (idx + j < n) ? g_counts[idx + j] : 0; s += v[j]; }
        int incl = s;
#pragma unroll
        for (int off = 1; off < 32; off <<= 1) {
            int y = __shfl_up_sync(0xffffffffu, incl, off);
            if (lane >= off) incl += y;
        }
        if (lane == 31) ws[warp] = incl;
        __syncthreads();
        if (warp == 0) {
            int wv = ws[lane];
            int winc = wv;
#pragma unroll
            for (int off = 1; off < 32; off <<= 1) {
                int y = __shfl_up_sync(0xffffffffu, winc, off);
                if (lane >= off) winc += y;
            }
            ws[lane] = winc - wv;
            if (lane == 31) s_total = winc;
        }
        __syncthreads();
        int running = s_carry + ws[warp] + (incl - s);
#pragma unroll
        for (int j = 0; j < 4; j++) {
            int i = idx + j;
            if (i < n) { g_row[i] = running; g_cursor[i] = running; g_counts[i] = 0; }
            running += v[j];
        }
        __syncthreads();
        if (t == 0) s_carry += s_total;
    }
    if (t == 0) g_row[n] = total;
}

__global__ void scatter_kernel(const int* __restrict__ ei, int E, int N) {
    int e = blockIdx.x * blockDim.x + threadIdx.x;
    int ET = E + N;
    if (e >= ET) return;
    int src, dst;
    if (e < E) { src = ei[e]; dst = ei[E + e]; }
    else       { src = e - E; dst = e - E; }
    int pos = atomicAdd(&g_cursor[dst], 1);
    g_srcs[pos] = src;
    g_dsts[pos] = dst;
}

// ------- per-edge weight precompute (device-global tables, coalesced I/O) ----
__global__ void weight1_kernel(int ET) {
    int e = blockIdx.x * blockDim.x + threadIdx.x;
    if (e >= ET) return;
    int s = g_srcs[e], d = g_dsts[e];
    float2 a = ((const float2*)g_asrc1)[s];
    float2 b = ((const float2*)g_adst1)[d];
    float l0 = a.x + b.x; l0 = l0 > 0.f ? l0 : 0.2f * l0;
    float l1 = a.y + b.y; l1 = l1 > 0.f ? l1 : 0.2f * l1;
    g_e1[e] = make_float4(__expf(l0), __expf(l1), __int_as_float(s), 0.f);
}

__global__ void weight2_kernel(int ET) {
    int e = blockIdx.x * blockDim.x + threadIdx.x;
    if (e >= ET) return;
    int s = g_srcs[e], d = g_dsts[e];
    float2 a = g_a2s[s];
    float2 b = g_a2d[d];
    float l0 = a.x + b.x; l0 = l0 > 0.f ? l0 : 0.2f * l0;
    float l1 = a.y + b.y; l1 = l1 > 0.f ? l1 : 0.2f * l1;
    g_e2[e] = make_float4(__expf(l0), __expf(l1), __int_as_float(s), 0.f);
}

// ------- GEMM1: g_h1h = half(x @ W1)  (+ fused layer-1 attention dots) -------
// (R12 scalar-FFMA inner loop — measured-best codegen)
__global__ void gemm1_kernel(const float* __restrict__ A, const float* __restrict__ B,
                             const float* __restrict__ att_src, const float* __restrict__ att_dst,
                             int M) {
    constexpr int BM = 64, BK = 32, BN = 128;
    constexpr int TX = 32, TY = 8, RPT = 8;
    __shared__ float As[BK][BM + 1];
    __shared__ float Bs[BK][BN];
    int t = threadIdx.x;
    int tx = t % TX, ty = t / TX;
    int row0 = blockIdx.x * BM;
    float acc[RPT][4];
#pragma unroll
    for (int r = 0; r < RPT; r++) { acc[r][0] = acc[r][1] = acc[r][2] = acc[r][3] = 0.f; }

    for (int k0 = 0; k0 < 128; k0 += BK) {
        for (int i = t; i < BM * BK; i += 256) {
            int r = i / BK, kk = i % BK;
            int gr = row0 + r;
            As[kk][r] = (gr < M) ? A[gr * 128 + k0 + kk] : 0.f;
        }
        for (int i = t; i < BK * BN; i += 256) {
            int kk = i / BN, c = i % BN;
            Bs[kk][c] = B[(k0 + kk) * BN + c];
        }
        __syncthreads();
#pragma unroll
        for (int kk = 0; kk < BK; kk++) {
            float4 bv = *(const float4*)&Bs[kk][tx * 4];
#pragma unroll
            for (int r = 0; r < RPT; r++) {
                float a = As[kk][ty * RPT + r];
                acc[r][0] = fmaf(a, bv.x, acc[r][0]);
                acc[r][1] = fmaf(a, bv.y, acc[r][1]);
                acc[r][2] = fmaf(a, bv.z, acc[r][2]);
                acc[r][3] = fmaf(a, bv.w, acc[r][3]);
            }
        }
        __syncthreads();
    }
    float4 asv = *(const float4*)&att_src[tx * 4];
    float4 adv = *(const float4*)&att_dst[tx * 4];
#pragma unroll
    for (int r = 0; r < RPT; r++) {
        int gr = row0 + ty * RPT + r;
        bool ok = gr < M;
        if (ok) {
            __half2 p0 = __floats2half2_rn(acc[r][0], acc[r][1]);
            __half2 p1 = __floats2half2_rn(acc[r][2], acc[r][3]);
            uint2 pk;
            pk.x = *(unsigned int*)&p0;
            pk.y = *(unsigned int*)&p1;
            *(uint2*)&g_h1h[gr * 128 + tx * 4] = pk;
        }
        float ps = acc[r][0] * asv.x + acc[r][1] * asv.y + acc[r][2] * asv.z + acc[r][3] * asv.w;
        float pd = acc[r][0] * adv.x + acc[r][1] * adv.y + acc[r][2] * adv.z + acc[r][3] * adv.w;
#pragma unroll
        for (int off = 1; off < 16; off <<= 1) {   // reduce within 16-lane halves (per head)
            ps += __shfl_xor_sync(0xffffffffu, ps, off);
            pd += __shfl_xor_sync(0xffffffffu, pd, off);
        }
        if ((tx & 15) == 0 && ok) {
            g_asrc1[gr * 2 + (tx >> 4)] = ps;
            g_adst1[gr * 2 + (tx >> 4)] = pd;
        }
    }
}

// ---------------- layer-1 softmax + aggregation + bias + ELU -----------------
__global__ void agg1_kernel(const float* __restrict__ b1, int N) {
    int gid = blockIdx.x * blockDim.x + threadIdx.x;
    int n = gid >> 5, lane = gid & 31;
    if (n >= N) return;
    int start = g_row[n], end = g_row[n + 1];
    int cb = lane * 4;
    bool head1 = lane >= 16;

    // single pass: uniform edge-record loads; every lane sums the denominators
    float a0 = 0.f, a1 = 0.f, a2 = 0.f, a3 = 0.f, s0 = 0.f, s1 = 0.f;
    int i = start;
    for (; i + 3 < end; i += 4) {
#pragma unroll
        for (int j = 0; j < 4; j++) {
            float4 e = g_e1[i + j];
            int s = __float_as_int(e.z);
            s0 += e.x; s1 += e.y;
            float w = head1 ? e.y : e.x;
            uint2 raw = *(const uint2*)&g_h1h[s * 128 + cb];
            float2 f0 = __half22float2(*(__half2*)&raw.x);
            float2 f1 = __half22float2(*(__half2*)&raw.y);
            a0 = fmaf(w, f0.x, a0);
            a1 = fmaf(w, f0.y, a1);
            a2 = fmaf(w, f1.x, a2);
            a3 = fmaf(w, f1.y, a3);
        }
    }
    for (; i < end; i++) {
        float4 e = g_e1[i];
        int s = __float_as_int(e.z);
        s0 += e.x; s1 += e.y;
        float w = head1 ? e.y : e.x;
        uint2 raw = *(const uint2*)&g_h1h[s * 128 + cb];
        float2 f0 = __half22float2(*(__half2*)&raw.x);
        float2 f1 = __half22float2(*(__half2*)&raw.y);
        a0 = fmaf(w, f0.x, a0);
        a1 = fmaf(w, f0.y, a1);
        a2 = fmaf(w, f1.x, a2);
        a3 = fmaf(w, f1.y, a3);
    }
    float inv = 1.f / ((head1 ? s1 : s0) + 1e-16f);
    float4 bb = *(const float4*)&b1[cb];
    float o0 = a0 * inv + bb.x; o0 = o0 > 0.f ? o0 : __expf(o0) - 1.f;
    float o1 = a1 * inv + bb.y; o1 = o1 > 0.f ? o1 : __expf(o1) - 1.f;
    float o2 = a2 * inv + bb.z; o2 = o2 > 0.f ? o2 : __expf(o2) - 1.f;
    float o3 = a3 * inv + bb.w; o3 = o3 > 0.f ? o3 : __expf(o3) - 1.f;
    *(float4*)&g_h2[n * 128 + cb] = make_float4(o0, o1, o2, o3);
}

// ------- fused mu+lv GEMM: g_hmlh = half(h2 @ [Wmu | Wlv]) + dots ------------
// (R12 scalar-FFMA inner loop)
__global__ void gemm_mulv_kernel(const float* __restrict__ Bmu, const float* __restrict__ Blv,
                                 const float* __restrict__ asmu, const float* __restrict__ admu,
                                 const float* __restrict__ aslv, const float* __restrict__ adlv,
                                 int M) {
    constexpr int BM = 64, BK = 32, BN = 64;
    constexpr int TX = 16, TY = 16, RPT = 4;
    __shared__ float As[BK][BM + 1];
    __shared__ float Bs[BK][BN];
    int t = threadIdx.x;
    int tx = t % TX, ty = t / TX;
    int row0 = blockIdx.x * BM;
    float acc[RPT][4];
#pragma unroll
    for (int r = 0; r < RPT; r++) { acc[r][0] = acc[r][1] = acc[r][2] = acc[r][3] = 0.f; }

    for (int k0 = 0; k0 < 128; k0 += BK) {
        for (int i = t; i < BM * BK; i += 256) {
            int r = i / BK, kk = i % BK;
            int gr = row0 + r;
            As[kk][r] = (gr < M) ? g_h2[gr * 128 + k0 + kk] : 0.f;
        }
        for (int i = t; i < BK * BN; i += 256) {
            int kk = i / BN, c = i % BN;
            Bs[kk][c] = (c < 32) ? Bmu[(k0 + kk) * 32 + c] : Blv[(k0 + kk) * 32 + (c - 32)];
        }
        __syncthreads();
#pragma unroll
        for (int kk = 0; kk < BK; kk++) {
            float4 bv = *(const float4*)&Bs[kk][tx * 4];
#pragma unroll
            for (int r = 0; r < RPT; r++) {
                float a = As[kk][ty * RPT + r];
                acc[r][0] = fmaf(a, bv.x, acc[r][0]);
                acc[r][1] = fmaf(a, bv.y, acc[r][1]);
                acc[r][2] = fmaf(a, bv.z, acc[r][2]);
                acc[r][3] = fmaf(a, bv.w, acc[r][3]);
            }
        }
        __syncthreads();
    }
    bool islv = tx >= 8;
    int c0 = (tx * 4) & 31;   // channel base within the 32-dim latent
    float4 asv = islv ? *(const float4*)&aslv[c0] : *(const float4*)&asmu[c0];
    float4 adv = islv ? *(const float4*)&adlv[c0] : *(const float4*)&admu[c0];
#pragma unroll
    for (int r = 0; r < RPT; r++) {
        int gr = row0 + ty * RPT + r;
        bool ok = gr < M;
        if (ok) {
            // interleaved: mu channel c -> [gr*64 + 2c], lv channel c -> [gr*64 + 2c+1]
            g_hmlh[gr * 64 + 2 * (c0 + 0) + islv] = __float2half_rn(acc[r][0]);
            g_hmlh[gr * 64 + 2 * (c0 + 1) + islv] = __float2half_rn(acc[r][1]);
            g_hmlh[gr * 64 + 2 * (c0 + 2) + islv] = __float2half_rn(acc[r][2]);
            g_hmlh[gr * 64 + 2 * (c0 + 3) + islv] = __float2half_rn(acc[r][3]);
        }
        float ps = acc[r][0] * asv.x + acc[r][1] * asv.y + acc[r][2] * asv.z + acc[r][3] * asv.w;
        float pd = acc[r][0] * adv.x + acc[r][1] * adv.y + acc[r][2] * adv.z + acc[r][3] * adv.w;
#pragma unroll
        for (int off = 1; off < 8; off <<= 1) {    // reduce within 8-lane subgroup
            ps += __shfl_xor_sync(0xffffffffu, ps, off);
            pd += __shfl_xor_sync(0xffffffffu, pd, off);
        }
        float os = __shfl_xor_sync(0xffffffffu, ps, 8);  // grab the other net's sum
        float od = __shfl_xor_sync(0xffffffffu, pd, 8);
        if ((t & 15) == 0 && ok) {
            g_a2s[gr] = make_float2(ps, os);   // {mu, lv}
            g_a2d[gr] = make_float2(pd, od);
        }
    }
}

// ---------------- mu + lv softmax + aggregation (fused), writes output -------
__global__ void agg2_kernel(const float* __restrict__ bmu, const float* __restrict__ blv,
                            float* __restrict__ out, int N) {
    int gid = blockIdx.x * blockDim.x + threadIdx.x;
    int n = gid >> 5, lane = gid & 31;
    if (n >= N) return;
    int start = g_row[n], end = g_row[n + 1];

    float accm = 0.f, accl = 0.f, sm = 0.f, sl = 0.f;
    int i = start;
    for (; i + 3 < end; i += 4) {
#pragma unroll
        for (int j = 0; j < 4; j++) {
            float4 e = g_e2[i + j];
            int s = __float_as_int(e.z);
            sm += e.x; sl += e.y;
            __half2 hv = *(const __half2*)&g_hmlh[s * 64 + lane * 2];  // {mu_c, lv_c}
            float2 f = __half22float2(hv);
            accm = fmaf(e.x, f.x, accm);
            accl = fmaf(e.y, f.y, accl);
        }
    }
    for (; i < end; i++) {
        float4 e = g_e2[i];
        int s = __float_as_int(e.z);
        sm += e.x; sl += e.y;
        __half2 hv = *(const __half2*)&g_hmlh[s * 64 + lane * 2];
        float2 f = __half22float2(hv);
        accm = fmaf(e.x, f.x, accm);
        accl = fmaf(e.y, f.y, accl);
    }
    out[n * 32 + lane]          = accm / (sm + 1e-16f) + bmu[lane];
    out[N * 32 + n * 32 + lane] = accl / (sl + 1e-16f) + blv[lane];
}

// ---------------- launch -----------------------------------------------------
extern "C" void kernel_launch(void* const* d_in, const int* in_sizes, int n_in,
                              void* d_out, int out_size) {
    const float* x          = (const float*)d_in[0];
    const int*   ei         = (const int*)d_in[1];
    const float* W1         = (const float*)d_in[2];
    const float* att_src1   = (const float*)d_in[3];
    const float* att_dst1   = (const float*)d_in[4];
    const float* b1         = (const float*)d_in[5];
    const float* Wmu        = (const float*)d_in[6];
    const float* att_src_mu = (const float*)d_in[7];
    const float* att_dst_mu = (const float*)d_in[8];
    const float* bmu        = (const float*)d_in[9];
    const float* Wlv        = (const float*)d_in[10];
    const float* att_src_lv = (const float*)d_in[11];
    const float* att_dst_lv = (const float*)d_in[12];
    const float* blv        = (const float*)d_in[13];
    float* out = (float*)d_out;

    int N = in_sizes[0] / 128;
    int E = in_sizes[1] / 2;
    int ET = E + N;

    const int TB = 256;
    int warpBlocks = (N * 32 + TB - 1) / TB;
    int edgeBlocks = (ET + TB - 1) / TB;

    // lazily created once (on the uncaptured correctness call); reused in capture
    static cudaStream_t s1 = nullptr;
    static cudaEvent_t evFork = nullptr, evJoin = nullptr;
    if (s1 == nullptr) {
        cudaStreamCreateWithFlags(&s1, cudaStreamNonBlocking);
        cudaEventCreateWithFlags(&evFork, cudaEventDisableTiming);
        cudaEventCreateWithFlags(&evJoin, cudaEventDisableTiming);
    }

    // fork: CSR build on s1, gemm1 on the main stream, join before weight1
    cudaEventRecord(evFork, 0);
    cudaStreamWaitEvent(s1, evFork, 0);

    hist_kernel<<<edgeBlocks, TB, 0, s1>>>(ei, E, N);
    scan_kernel<<<1, 1024, 0, s1>>>(N, ET);
    scatter_kernel<<<edgeBlocks, TB, 0, s1>>>(ei, E, N);

    gemm1_kernel<<<(N + 63) / 64, TB>>>(x, W1, att_src1, att_dst1, N);

    cudaEventRecord(evJoin, s1);
    cudaStreamWaitEvent(0, evJoin, 0);

    // layer 1: per-edge weights, then lean aggregation
    weight1_kernel<<<edgeBlocks, TB>>>(ET);
    agg1_kernel<<<warpBlocks, TB>>>(b1, N);

    // mu + logvar: fused projection GEMM (+dots), weights, fused aggregation
    gemm_mulv_kernel<<<(N + 63) / 64, TB>>>(Wmu, Wlv, att_src_mu, att_dst_mu,
                                            att_src_lv, att_dst_lv, N);
    weight2_kernel<<<edgeBlocks, TB>>>(ET);
    agg2_kernel<<<warpBlocks, TB>>>(bmu, blv, out, N);
}

// round 15
// speedup vs baseline: 1.7813x; 1.2550x over previous
#include <cuda_runtime.h>
#include <cuda_fp16.h>

// ---------------- problem-size capacities (fixed by the dataset) -------------
#define MAXN 50000
#define MAXE 800000
#define MAXET (MAXN + MAXE)
#define SCAN_CHUNK 4096
#define MAXNB ((MAXN + SCAN_CHUNK - 1) / SCAN_CHUNK)

// ---------------- device scratch (no allocation allowed) ---------------------
__device__ __half g_h1h[MAXN * 128];   // x @ W1   (fp16, gather-only)
__device__ float  g_h2[MAXN * 128];    // elu(layer1 out)  (fp32, GEMM input)
__device__ __half g_hmlh[MAXN * 64];   // interleaved [mu_c, lv_c], fp16, gather-only
__device__ float  g_asrc1[MAXN * 2];   // layer1 per-node att dots (2 heads)
__device__ float  g_adst1[MAXN * 2];
__device__ float2 g_a2s[MAXN];         // {a_src_mu, a_src_lv}
__device__ float2 g_a2d[MAXN];         // {a_dst_mu, a_dst_lv}
__device__ int    g_counts[MAXN];      // STAYS ZERO between calls (final_scan cleans)
__device__ int    g_row[MAXN + 1];
__device__ int    g_cursor[MAXN];
__device__ int    g_srcs[MAXET];       // CSR (by dst) of source node ids
__device__ int    g_dsts[MAXET];       // CSR slot -> dst node id
__device__ int    g_part[MAXNB + 1];
__device__ float4 g_e1[MAXET];         // per-edge {w0, w1, src_bits, -} layer 1
__device__ float4 g_e2[MAXET];         // per-edge {wmu, wlv, src_bits, -} layer 2

// ---------------- CSR build --------------------------------------------------
__global__ void hist_kernel(const int* __restrict__ ei, int E, int N) {
    int e = blockIdx.x * blockDim.x + threadIdx.x;
    int ET = E + N;
    if (e >= ET) return;
    int dst = (e < E) ? ei[E + e] : (e - E);   // self-loop tail
    atomicAdd(&g_counts[dst], 1);
}

__global__ void block_sum_kernel(int n) {
    int t = threadIdx.x;
    int base = blockIdx.x * SCAN_CHUNK + t * 4;
    int s = 0;
#pragma unroll
    for (int j = 0; j < 4; j++) { int i = base + j; if (i < n) s += g_counts[i]; }
#pragma unroll
    for (int off = 16; off; off >>= 1) s += __shfl_xor_sync(0xffffffffu, s, off);
    __shared__ int ws[32];
    if ((t & 31) == 0) ws[t >> 5] = s;
    __syncthreads();
    if (t < 32) {
        int v = ws[t];
#pragma unroll
        for (int off = 16; off; off >>= 1) v += __shfl_xor_sync(0xffffffffu, v, off);
        if (t == 0) g_part[blockIdx.x] = v;
    }
}

// per-block scan + in-kernel partial-block offset; also zeroes g_counts
__global__ void final_scan_kernel(int n, int nb, int total) {
    int t = threadIdx.x, lane = t & 31, warp = t >> 5;
    __shared__ int s_partoff;
    __shared__ int ws[32];
    if (t < 32) {
        int v = (lane < nb && lane < blockIdx.x) ? g_part[lane] : 0;
#pragma unroll
        for (int off = 16; off; off >>= 1) v += __shfl_xor_sync(0xffffffffu, v, off);
        if (lane == 0) s_partoff = v;
    }
    int base = blockIdx.x * SCAN_CHUNK + t * 4;
    int v[4]; int s = 0;
#pragma unroll
    for (int j = 0; j < 4; j++) { int i = base + j; v[j] = (i < n) ? g_counts[i] : 0; s += v[j]; }
    int incl = s;
#pragma unroll
    for (int off = 1; off < 32; off <<= 1) {
        int y = __shfl_up_sync(0xffffffffu, incl, off);
        if (lane >= off) incl += y;
    }
    if (lane == 31) ws[warp] = incl;
    __syncthreads();
    if (warp == 0) {
        int wv = ws[lane];
        int winc = wv;
#pragma unroll
        for (int off = 1; off < 32; off <<= 1) {
            int y = __shfl_up_sync(0xffffffffu, winc, off);
            if (lane >= off) winc += y;
        }
        ws[lane] = winc - wv;
    }
    __syncthreads();
    int running = s_partoff + ws[warp] + (incl - s);
#pragma unroll
    for (int j = 0; j < 4; j++) {
        int i = base + j;
        if (i < n) { g_row[i] = running; g_cursor[i] = running; g_counts[i] = 0; }
        running += v[j];
    }
    if (blockIdx.x == 0 && t == 0) g_row[n] = total;
}

__global__ void scatter_kernel(const int* __restrict__ ei, int E, int N) {
    int e = blockIdx.x * blockDim.x + threadIdx.x;
    int ET = E + N;
    if (e >= ET) return;
    int src, dst;
    if (e < E) { src = ei[e]; dst = ei[E + e]; }
    else       { src = e - E; dst = e - E; }
    int pos = atomicAdd(&g_cursor[dst], 1);
    g_srcs[pos] = src;
    g_dsts[pos] = dst;
}

// ------- per-edge weight precompute (device-global tables, coalesced I/O) ----
__global__ void weight1_kernel(int ET) {
    int e = blockIdx.x * blockDim.x + threadIdx.x;
    if (e >= ET) return;
    int s = g_srcs[e], d = g_dsts[e];
    float2 a = ((const float2*)g_asrc1)[s];
    float2 b = ((const float2*)g_adst1)[d];
    float l0 = a.x + b.x; l0 = l0 > 0.f ? l0 : 0.2f * l0;
    float l1 = a.y + b.y; l1 = l1 > 0.f ? l1 : 0.2f * l1;
    g_e1[e] = make_float4(__expf(l0), __expf(l1), __int_as_float(s), 0.f);
}

__global__ void weight2_kernel(int ET) {
    int e = blockIdx.x * blockDim.x + threadIdx.x;
    if (e >= ET) return;
    int s = g_srcs[e], d = g_dsts[e];
    float2 a = g_a2s[s];
    float2 b = g_a2d[d];
    float l0 = a.x + b.x; l0 = l0 > 0.f ? l0 : 0.2f * l0;
    float l1 = a.y + b.y; l1 = l1 > 0.f ? l1 : 0.2f * l1;
    g_e2[e] = make_float4(__expf(l0), __expf(l1), __int_as_float(s), 0.f);
}

// ------- GEMM1: g_h1h = half(x @ W1)  (+ fused layer-1 attention dots) -------
__global__ void __launch_bounds__(256, 4)
gemm1_kernel(const float* __restrict__ A, const float* __restrict__ B,
             const float* __restrict__ att_src, const float* __restrict__ att_dst,
             int M) {
    constexpr int BM = 64, BK = 32, BN = 128;
    constexpr int TX = 32, TY = 8, RPT = 8;
    __shared__ __align__(16) float As[BK][BM + 4];   // row = 272B, 16B-aligned
    __shared__ __align__(16) float Bs[BK][BN];
    int t = threadIdx.x;
    int tx = t % TX, ty = t / TX;
    int row0 = blockIdx.x * BM;
    float acc[RPT][4];
#pragma unroll
    for (int r = 0; r < RPT; r++) { acc[r][0] = acc[r][1] = acc[r][2] = acc[r][3] = 0.f; }

    for (int k0 = 0; k0 < 128; k0 += BK) {
        for (int i = t; i < BM * BK; i += 256) {
            int r = i / BK, kk = i % BK;
            int gr = row0 + r;
            As[kk][r] = (gr < M) ? A[gr * 128 + k0 + kk] : 0.f;
        }
        for (int i = t; i < BK * BN; i += 256) {
            int kk = i / BN, c = i % BN;
            Bs[kk][c] = B[(k0 + kk) * BN + c];
        }
        __syncthreads();
#pragma unroll
        for (int kk = 0; kk < BK; kk++) {
            float4 bv = *(const float4*)&Bs[kk][tx * 4];
            // 8 contiguous A values for this thread: 2 x LDS.128 (warp-broadcast)
            const float4* ap = (const float4*)&As[kk][ty * RPT];
            float4 av0 = ap[0], av1 = ap[1];
            float a[8] = {av0.x, av0.y, av0.z, av0.w, av1.x, av1.y, av1.z, av1.w};
#pragma unroll
            for (int r = 0; r < RPT; r++) {
                acc[r][0] = fmaf(a[r], bv.x, acc[r][0]);
                acc[r][1] = fmaf(a[r], bv.y, acc[r][1]);
                acc[r][2] = fmaf(a[r], bv.z, acc[r][2]);
                acc[r][3] = fmaf(a[r], bv.w, acc[r][3]);
            }
        }
        __syncthreads();
    }
    float4 asv = *(const float4*)&att_src[tx * 4];
    float4 adv = *(const float4*)&att_dst[tx * 4];
#pragma unroll
    for (int r = 0; r < RPT; r++) {
        int gr = row0 + ty * RPT + r;
        bool ok = gr < M;
        if (ok) {
            __half2 p0 = __floats2half2_rn(acc[r][0], acc[r][1]);
            __half2 p1 = __floats2half2_rn(acc[r][2], acc[r][3]);
            uint2 pk;
            pk.x = *(unsigned int*)&p0;
            pk.y = *(unsigned int*)&p1;
            *(uint2*)&g_h1h[gr * 128 + tx * 4] = pk;
        }
        float ps = acc[r][0] * asv.x + acc[r][1] * asv.y + acc[r][2] * asv.z + acc[r][3] * asv.w;
        float pd = acc[r][0] * adv.x + acc[r][1] * adv.y + acc[r][2] * adv.z + acc[r][3] * adv.w;
#pragma unroll
        for (int off = 1; off < 16; off <<= 1) {   // reduce within 16-lane halves (per head)
            ps += __shfl_xor_sync(0xffffffffu, ps, off);
            pd += __shfl_xor_sync(0xffffffffu, pd, off);
        }
        if ((tx & 15) == 0 && ok) {
            g_asrc1[gr * 2 + (tx >> 4)] = ps;
            g_adst1[gr * 2 + (tx >> 4)] = pd;
        }
    }
}

// ---------------- layer-1 softmax + aggregation + bias + ELU -----------------
__global__ void agg1_kernel(const float* __restrict__ b1, int N) {
    int gid = blockIdx.x * blockDim.x + threadIdx.x;
    int n = gid >> 5, lane = gid & 31;
    if (n >= N) return;
    int start = g_row[n], end = g_row[n + 1];
    int cb = lane * 4;
    bool head1 = lane >= 16;

    float a0 = 0.f, a1 = 0.f, a2 = 0.f, a3 = 0.f, s0 = 0.f, s1 = 0.f;
    int i = start;
    for (; i + 3 < end; i += 4) {
#pragma unroll
        for (int j = 0; j < 4; j++) {
            float4 e = g_e1[i + j];
            int s = __float_as_int(e.z);
            s0 += e.x; s1 += e.y;
            float w = head1 ? e.y : e.x;
            uint2 raw = *(const uint2*)&g_h1h[s * 128 + cb];
            float2 f0 = __half22float2(*(__half2*)&raw.x);
            float2 f1 = __half22float2(*(__half2*)&raw.y);
            a0 = fmaf(w, f0.x, a0);
            a1 = fmaf(w, f0.y, a1);
            a2 = fmaf(w, f1.x, a2);
            a3 = fmaf(w, f1.y, a3);
        }
    }
    for (; i < end; i++) {
        float4 e = g_e1[i];
        int s = __float_as_int(e.z);
        s0 += e.x; s1 += e.y;
        float w = head1 ? e.y : e.x;
        uint2 raw = *(const uint2*)&g_h1h[s * 128 + cb];
        float2 f0 = __half22float2(*(__half2*)&raw.x);
        float2 f1 = __half22float2(*(__half2*)&raw.y);
        a0 = fmaf(w, f0.x, a0);
        a1 = fmaf(w, f0.y, a1);
        a2 = fmaf(w, f1.x, a2);
        a3 = fmaf(w, f1.y, a3);
    }
    float inv = 1.f / ((head1 ? s1 : s0) + 1e-16f);
    float4 bb = *(const float4*)&b1[cb];
    float o0 = a0 * inv + bb.x; o0 = o0 > 0.f ? o0 : __expf(o0) - 1.f;
    float o1 = a1 * inv + bb.y; o1 = o1 > 0.f ? o1 : __expf(o1) - 1.f;
    float o2 = a2 * inv + bb.z; o2 = o2 > 0.f ? o2 : __expf(o2) - 1.f;
    float o3 = a3 * inv + bb.w; o3 = o3 > 0.f ? o3 : __expf(o3) - 1.f;
    *(float4*)&g_h2[n * 128 + cb] = make_float4(o0, o1, o2, o3);
}

// ------- fused mu+lv GEMM: g_hmlh = half(h2 @ [Wmu | Wlv]) + dots ------------
__global__ void gemm_mulv_kernel(const float* __restrict__ Bmu, const float* __restrict__ Blv,
                                 const float* __restrict__ asmu, const float* __restrict__ admu,
                                 const float* __restrict__ aslv, const float* __restrict__ adlv,
                                 int M) {
    constexpr int BM = 64, BK = 32, BN = 64;
    constexpr int TX = 16, TY = 16, RPT = 4;
    __shared__ __align__(16) float As[BK][BM + 4];
    __shared__ __align__(16) float Bs[BK][BN];
    int t = threadIdx.x;
    int tx = t % TX, ty = t / TX;
    int row0 = blockIdx.x * BM;
    float acc[RPT][4];
#pragma unroll
    for (int r = 0; r < RPT; r++) { acc[r][0] = acc[r][1] = acc[r][2] = acc[r][3] = 0.f; }

    for (int k0 = 0; k0 < 128; k0 += BK) {
        for (int i = t; i < BM * BK; i += 256) {
            int r = i / BK, kk = i % BK;
            int gr = row0 + r;
            As[kk][r] = (gr < M) ? g_h2[gr * 128 + k0 + kk] : 0.f;
        }
        for (int i = t; i < BK * BN; i += 256) {
            int kk = i / BN, c = i % BN;
            Bs[kk][c] = (c < 32) ? Bmu[(k0 + kk) * 32 + c] : Blv[(k0 + kk) * 32 + (c - 32)];
        }
        __syncthreads();
#pragma unroll
        for (int kk = 0; kk < BK; kk++) {
            float4 bv = *(const float4*)&Bs[kk][tx * 4];
            float4 av = *(const float4*)&As[kk][ty * RPT];   // 1 x LDS.128 broadcast
            float a[4] = {av.x, av.y, av.z, av.w};
#pragma unroll
            for (int r = 0; r < RPT; r++) {
                acc[r][0] = fmaf(a[r], bv.x, acc[r][0]);
                acc[r][1] = fmaf(a[r], bv.y, acc[r][1]);
                acc[r][2] = fmaf(a[r], bv.z, acc[r][2]);
                acc[r][3] = fmaf(a[r], bv.w, acc[r][3]);
            }
        }
        __syncthreads();
    }
    bool islv = tx >= 8;
    int c0 = (tx * 4) & 31;   // channel base within the 32-dim latent
    float4 asv = islv ? *(const float4*)&aslv[c0] : *(const float4*)&asmu[c0];
    float4 adv = islv ? *(const float4*)&adlv[c0] : *(const float4*)&admu[c0];
#pragma unroll
    for (int r = 0; r < RPT; r++) {
        int gr = row0 + ty * RPT + r;
        bool ok = gr < M;
        if (ok) {
            // interleaved: mu channel c -> [gr*64 + 2c], lv channel c -> [gr*64 + 2c+1]
            g_hmlh[gr * 64 + 2 * (c0 + 0) + islv] = __float2half_rn(acc[r][0]);
            g_hmlh[gr * 64 + 2 * (c0 + 1) + islv] = __float2half_rn(acc[r][1]);
            g_hmlh[gr * 64 + 2 * (c0 + 2) + islv] = __float2half_rn(acc[r][2]);
            g_hmlh[gr * 64 + 2 * (c0 + 3) + islv] = __float2half_rn(acc[r][3]);
        }
        float ps = acc[r][0] * asv.x + acc[r][1] * asv.y + acc[r][2] * asv.z + acc[r][3] * asv.w;
        float pd = acc[r][0] * adv.x + acc[r][1] * adv.y + acc[r][2] * adv.z + acc[r][3] * adv.w;
#pragma unroll
        for (int off = 1; off < 8; off <<= 1) {    // reduce within 8-lane subgroup
            ps += __shfl_xor_sync(0xffffffffu, ps, off);
            pd += __shfl_xor_sync(0xffffffffu, pd, off);
        }
        float os = __shfl_xor_sync(0xffffffffu, ps, 8);  // grab the other net's sum
        float od = __shfl_xor_sync(0xffffffffu, pd, 8);
        if ((t & 15) == 0 && ok) {
            g_a2s[gr] = make_float2(ps, os);   // {mu, lv}
            g_a2d[gr] = make_float2(pd, od);
        }
    }
}

// ---------------- mu + lv softmax + aggregation (fused), writes output -------
__global__ void agg2_kernel(const float* __restrict__ bmu, const float* __restrict__ blv,
                            float* __restrict__ out, int N) {
    int gid = blockIdx.x * blockDim.x + threadIdx.x;
    int n = gid >> 5, lane = gid & 31;
    if (n >= N) return;
    int start = g_row[n], end = g_row[n + 1];

    float accm = 0.f, accl = 0.f, sm = 0.f, sl = 0.f;
    int i = start;
    for (; i + 3 < end; i += 4) {
#pragma unroll
        for (int j = 0; j < 4; j++) {
            float4 e = g_e2[i + j];
            int s = __float_as_int(e.z);
            sm += e.x; sl += e.y;
            __half2 hv = *(const __half2*)&g_hmlh[s * 64 + lane * 2];  // {mu_c, lv_c}
            float2 f = __half22float2(hv);
            accm = fmaf(e.x, f.x, accm);
            accl = fmaf(e.y, f.y, accl);
        }
    }
    for (; i < end; i++) {
        float4 e = g_e2[i];
        int s = __float_as_int(e.z);
        sm += e.x; sl += e.y;
        __half2 hv = *(const __half2*)&g_hmlh[s * 64 + lane * 2];
        float2 f = __half22float2(hv);
        accm = fmaf(e.x, f.x, accm);
        accl = fmaf(e.y, f.y, accl);
    }
    out[n * 32 + lane]          = accm / (sm + 1e-16f) + bmu[lane];
    out[N * 32 + n * 32 + lane] = accl / (sl + 1e-16f) + blv[lane];
}

// ---------------- launch -----------------------------------------------------
extern "C" void kernel_launch(void* const* d_in, const int* in_sizes, int n_in,
                              void* d_out, int out_size) {
    const float* x          = (const float*)d_in[0];
    const int*   ei         = (const int*)d_in[1];
    const float* W1         = (const float*)d_in[2];
    const float* att_src1   = (const float*)d_in[3];
    const float* att_dst1   = (const float*)d_in[4];
    const float* b1         = (const float*)d_in[5];
    const float* Wmu        = (const float*)d_in[6];
    const float* att_src_mu = (const float*)d_in[7];
    const float* att_dst_mu = (const float*)d_in[8];
    const float* bmu        = (const float*)d_in[9];
    const float* Wlv        = (const float*)d_in[10];
    const float* att_src_lv = (const float*)d_in[11];
    const float* att_dst_lv = (const float*)d_in[12];
    const float* blv        = (const float*)d_in[13];
    float* out = (float*)d_out;

    int N = in_sizes[0] / 128;
    int E = in_sizes[1] / 2;
    int ET = E + N;
    int NB = (N + SCAN_CHUNK - 1) / SCAN_CHUNK;

    const int TB = 256;
    int warpBlocks = (N * 32 + TB - 1) / TB;
    int edgeBlocks = (ET + TB - 1) / TB;

    // lazily created once (on the uncaptured correctness call); reused in capture
    static cudaStream_t s1 = nullptr;
    static cudaEvent_t evFork = nullptr, evJoin = nullptr;
    if (s1 == nullptr) {
        cudaStreamCreateWithFlags(&s1, cudaStreamNonBlocking);
        cudaEventCreateWithFlags(&evFork, cudaEventDisableTiming);
        cudaEventCreateWithFlags(&evJoin, cudaEventDisableTiming);
    }

    // fork: CSR build on s1, gemm1 on the main stream, join before weight1
    cudaEventRecord(evFork, 0);
    cudaStreamWaitEvent(s1, evFork, 0);

    hist_kernel<<<edgeBlocks, TB, 0, s1>>>(ei, E, N);
    block_sum_kernel<<<NB, 1024, 0, s1>>>(N);
    final_scan_kernel<<<NB, 1024, 0, s1>>>(N, NB, ET);
    scatter_kernel<<<edgeBlocks, TB, 0, s1>>>(ei, E, N);

    gemm1_kernel<<<(N + 63) / 64, TB>>>(x, W1, att_src1, att_dst1, N);

    cudaEventRecord(evJoin, s1);
    cudaStreamWaitEvent(0, evJoin, 0);

    // layer 1: per-edge weights, then lean aggregation
    weight1_kernel<<<edgeBlocks, TB>>>(ET);
    agg1_kernel<<<warpBlocks, TB>>>(b1, N);

    // mu + logvar: fused projection GEMM (+dots), weights, fused aggregation
    gemm_mulv_kernel<<<(N + 63) / 64, TB>>>(Wmu, Wlv, att_src_mu, att_dst_mu,
                                            att_src_lv, att_dst_lv, N);
    weight2_kernel<<<edgeBlocks, TB>>>(ET);
    agg2_kernel<<<warpBlocks, TB>>>(bmu, blv, out, N);
}